// round 15
// baseline (speedup 1.0000x reference)
#include <cuda_runtime.h>
#include <cuda_fp16.h>
#include <cstdint>

#define SQRT2F 1.41421356237309515f
#define INV_SQRT2F 0.70710678118654752f

// ---------------- scratch ----------------
__device__ __align__(16) __half   g_xh  [8ull * 4096 * 256];     // x NHWC f16
__device__ __align__(16) __half   g_t1h [8ull * 4096 * 256];     // conv1 out NHWC f16
__device__ __align__(16) __half   g_uph [8ull * 16384 * 256];    // upsampled NHWC f16
__device__ __align__(16) float    g_skip[8ull * 128 * 64 * 64];  // skip 64^2 fp32 NCHW
__device__ __align__(16) uint32_t g_w1L [2ull * 16 * 9 * 1536];  // 128-co-block images
__device__ __align__(16) uint32_t g_w2L [1ull * 16 * 9 * 1536];
__device__ __align__(16) uint32_t g_wskL[2ull * 16 * 1 * 768];   // 64-co-block image

// ---------------- helpers ----------------
__device__ __forceinline__ uint32_t smem_u32(const void* p)
{ return (uint32_t)__cvta_generic_to_shared(p); }

__device__ __forceinline__ void mma_f16(float* c, const uint32_t* a, const uint32_t* b)
{
    asm volatile(
        "mma.sync.aligned.m16n8k16.row.col.f32.f16.f16.f32 "
        "{%0,%1,%2,%3}, {%4,%5,%6,%7}, {%8,%9}, {%0,%1,%2,%3};"
        : "+f"(c[0]), "+f"(c[1]), "+f"(c[2]), "+f"(c[3])
        : "r"(a[0]), "r"(a[1]), "r"(a[2]), "r"(a[3]), "r"(b[0]), "r"(b[1]));
}

__device__ __forceinline__ void ldsm4(uint32_t* r, uint32_t addr)
{
    asm volatile("ldmatrix.sync.aligned.m8n8.x4.shared.b16 {%0,%1,%2,%3}, [%4];"
                 : "=r"(r[0]), "=r"(r[1]), "=r"(r[2]), "=r"(r[3]) : "r"(addr));
}

__device__ __forceinline__ void cp16(void* d, const void* s)
{ asm volatile("cp.async.cg.shared.global [%0], [%1], 16;" :: "r"(smem_u32(d)), "l"(s)); }
__device__ __forceinline__ void cp16z(void* d, const void* s, bool ok)
{ int sz = ok ? 16 : 0;
  asm volatile("cp.async.cg.shared.global [%0], [%1], 16, %2;" :: "r"(smem_u32(d)), "l"(s), "r"(sz)); }
__device__ __forceinline__ void cpc() { asm volatile("cp.async.commit_group;"); }
template <int N> __device__ __forceinline__ void cpw()
{ asm volatile("cp.async.wait_group %0;" :: "n"(N)); }

__device__ __forceinline__ void up_taps(int o, int lim, int& a, int& b, float& fa, float& fb)
{
    int i = o >> 1;
    if (o & 1) { a = i; b = (i + 1 < lim) ? i + 1 : lim; fa = 0.75f; fb = 0.25f; }
    else       { a = (i - 1 > 0) ? i - 1 : 0; b = i;     fa = 0.25f; fb = 0.75f; }
}

// ---------------- prep: x NCHW fp32 -> NHWC f16 ----------------
__global__ void pack_x_nhwc(const float* __restrict__ src, __half* __restrict__ dst)
{
    __shared__ float tile[32][33];
    int n = blockIdx.z, c0 = blockIdx.y * 32, p0 = blockIdx.x * 32;
    int tx = threadIdx.x, ty = threadIdx.y;
    const float* S = src + (size_t)n * 256 * 4096;
    __half* D = dst + (size_t)n * 4096 * 256;
#pragma unroll
    for (int i = 0; i < 32; i += 8) tile[ty + i][tx] = S[(size_t)(c0 + ty + i) * 4096 + p0 + tx];
    __syncthreads();
#pragma unroll
    for (int i = 0; i < 32; i += 8)
        D[(size_t)(p0 + ty + i) * 256 + c0 + tx] = __float2half(tile[tx][ty + i]);
}

// ---------------- prep: weights -> padded co-major smem image (coW-co blocks) ----------------
__global__ void wL_prep(const float* __restrict__ w, uint32_t* __restrict__ dst,
                        int ks2, float scale, int coW, int total)
{
    int idx = blockIdx.x * 256 + threadIdx.x;
    if (idx >= total) return;
    int j  = idx & 7;
    int t1 = idx >> 3;
    int co = t1 % coW;
    int t2 = t1 / coW;
    int tap   = t2 % ks2;
    int t3    = t2 / ks2;
    int chunk = t3 & 15;
    int coblk = t3 >> 4;
    int cog = coblk * coW + co;
    int ci  = chunk * 16 + 2 * j;
    float lo = w[((size_t)cog * 256 + ci) * ks2 + tap] * scale;
    float hi = w[((size_t)cog * 256 + ci + 1) * ks2 + tap] * scale;
    __half2 h = __floats2half2_rn(lo, hi);
    dst[(size_t)t2 * coW * 12 + co * 12 + j] = *reinterpret_cast<uint32_t*>(&h);
}

// ---------------- upsample: NHWC f16 64^2 -> NHWC f16 128^2 ----------------
__global__ void upsample_h16(const uint32_t* __restrict__ src, uint32_t* __restrict__ dst)
{
    int idx = blockIdx.x * 256 + threadIdx.x;
    int n = idx >> 21, rem = idx & 2097151;
    int px = rem >> 7, j = rem & 127;
    int oh = px >> 7, ow = px & 127;
    int ha, hb, wa, wb; float fha, fhb, fwa, fwb;
    up_taps(oh, 63, ha, hb, fha, fhb);
    up_taps(ow, 63, wa, wb, fwa, fwb);
    const uint32_t* S = src + (size_t)n * 4096 * 128;
    float2 aa = __half22float2(*(const __half2*)&S[(ha * 64 + wa) * 128 + j]);
    float2 ab = __half22float2(*(const __half2*)&S[(ha * 64 + wb) * 128 + j]);
    float2 ba = __half22float2(*(const __half2*)&S[(hb * 64 + wa) * 128 + j]);
    float2 bb = __half22float2(*(const __half2*)&S[(hb * 64 + wb) * 128 + j]);
    float v0 = fha * (fwa * aa.x + fwb * ab.x) + fhb * (fwa * ba.x + fwb * bb.x);
    float v1 = fha * (fwa * aa.y + fwb * ab.y) + fhb * (fwa * ba.y + fwb * bb.y);
    __half2 h = __floats2half2_rn(v0, v1);
    dst[idx] = *reinterpret_cast<uint32_t*>(&h);
}

// ---------------- f16 implicit-GEMM conv: wide warp tile, 3-stage cp.async ----------------
// CTA: (TH rows x 64 cols) px x (NF*16) co. Warp: 64 px x (NF*8) co = 4 x NF m16n8k16.
template <int TH, int W, int KS, int COUT, int NF, bool ACT, bool FUSE, bool OUT16>
__global__ __launch_bounds__(256, NF == 8 ? 1 : 2)
void conv_lds(const __half* __restrict__ xin, const uint32_t* __restrict__ wL,
              const float* __restrict__ bias, const float* __restrict__ skip64,
              float* __restrict__ outp)
{
    constexpr int KS2   = KS * KS;
    constexpr int PAD   = (KS == 3) ? 1 : 0;
    constexpr int XR    = TH + KS - 1;
    constexpr int CW    = 64 + 2 * PAD;
    constexpr int COW   = NF * 16;            // co per CTA
    constexpr int WSTG  = KS2 * COW * 12;     // u32
    constexpr int XSTG  = XR * CW * 12;       // u32
    constexpr int STAGE = WSTG + XSTG;
    constexpr int NCH   = 16;

    extern __shared__ uint32_t smemu[];

    const int tid = threadIdx.x, lane = tid & 31, warp = tid >> 5;
    const int warpM = warp & 3, warpN = warp >> 2;
    const int n = blockIdx.z, coBase = blockIdx.y * COW;
    constexpr int tilesX = W / 64;
    const int colBase = (blockIdx.x % tilesX) * 64;
    const int rowBase = (blockIdx.x / tilesX) * TH;

    const __half* xN = xin + (size_t)n * W * W * 256;

    const int aLane = ((lane & 7) + ((lane >> 3) & 1) * 8) * 12 + (lane >> 4) * 4;
    const int bLane = ((lane & 7) + (lane >> 4) * 8) * 12 + ((lane >> 3) & 1) * 4;

    auto stage = [&](int ch) {
        uint32_t* base = smemu + (ch % 3) * STAGE;
        uint32_t* Wsb = base;
        uint32_t* Xsb = base + WSTG;
        const uint32_t* ws = wL + ((size_t)(blockIdx.y * 16 + ch) * KS2) * (COW * 12);
#pragma unroll
        for (int i = tid; i < KS2 * COW * 2; i += 256) {
            int c16 = i & 1, co = (i >> 1) % COW, tap = (i >> 1) / COW;
            int off = (tap * COW + co) * 12 + c16 * 4;
            cp16(Wsb + off, ws + off);
        }
        const int ciB = ch * 16;
#pragma unroll
        for (int i = tid; i < XR * CW * 2; i += 256) {
            int p = i >> 1, g8 = i & 1;
            int hr = p / CW, hc = p - hr * CW;
            int gy = rowBase + hr - PAD, gx = colBase + hc - PAD;
            bool ok = ((unsigned)gy < (unsigned)W) && ((unsigned)gx < (unsigned)W);
            const __half* s = ok ? xN + ((size_t)gy * W + gx) * 256 + ciB + g8 * 8 : xN;
            cp16z(Xsb + p * 12 + g8 * 4, s, ok);
        }
    };

    float acc[4][NF][4];
#pragma unroll
    for (int i = 0; i < 4; i++)
#pragma unroll
        for (int j = 0; j < NF; j++)
#pragma unroll
            for (int k = 0; k < 4; k++) acc[i][j][k] = 0.f;

    stage(0); cpc();
    stage(1); cpc();

    for (int c = 0; c < NCH; c++) {
        if (c + 1 < NCH) cpw<1>(); else cpw<0>();
        __syncthreads();
        if (c + 2 < NCH) { stage(c + 2); cpc(); }   // buffer (c+2)%3 freed by this barrier

        uint32_t* base = smemu + (c % 3) * STAGE;
        const uint32_t wB0 = smem_u32(base) + bLane * 4;
        const uint32_t xB0 = smem_u32(base + WSTG) + aLane * 4;

#pragma unroll
        for (int ky = 0; ky < KS; ky++)
#pragma unroll
            for (int kx = 0; kx < KS; kx++) {
                const int tap = ky * KS + kx;
                const int rowOff = ((warpM + ky) * CW + kx) * 48;
                uint32_t a[4][4], bf[NF][2];
#pragma unroll
                for (int mf = 0; mf < 4; mf++)
                    ldsm4(a[mf], xB0 + rowOff + mf * 768);
#pragma unroll
                for (int np = 0; np < NF / 2; np++) {
                    uint32_t r[4];
                    ldsm4(r, wB0 + tap * (COW * 48) + (warpN * (COW / 2) + np * 16) * 48);
                    bf[np * 2][0] = r[0]; bf[np * 2][1] = r[1];
                    bf[np * 2 + 1][0] = r[2]; bf[np * 2 + 1][1] = r[3];
                }
#pragma unroll
                for (int mf = 0; mf < 4; mf++)
#pragma unroll
                    for (int nf = 0; nf < NF; nf++)
                        mma_f16(acc[mf][nf], a[mf], bf[nf]);
            }
    }
    __syncthreads();

    const int g = lane >> 2, t = lane & 3;

    if (OUT16) {
        // NHWC f16 out via smem transpose: stride 68 u32/px, banks 4g+t conflict-free
        uint32_t* tileo = smemu;
        float bv0[NF], bv1[NF];
#pragma unroll
        for (int nf = 0; nf < NF; nf++) {
            int co = coBase + warpN * (NF * 8) + nf * 8 + t * 2;
            bv0[nf] = ACT ? __ldg(&bias[co]) : 0.f;
            bv1[nf] = ACT ? __ldg(&bias[co + 1]) : 0.f;
        }
#pragma unroll
        for (int mf = 0; mf < 4; mf++)
#pragma unroll
            for (int h = 0; h < 2; h++) {
                const int gx = mf * 16 + g + h * 8;
#pragma unroll
                for (int nf = 0; nf < NF; nf++) {
                    float v0 = acc[mf][nf][h * 2 + 0] + bv0[nf];
                    float v1 = acc[mf][nf][h * 2 + 1] + bv1[nf];
                    if (ACT) {
                        v0 *= (v0 >= 0.f) ? SQRT2F : (0.2f * SQRT2F);
                        v1 *= (v1 >= 0.f) ? SQRT2F : (0.2f * SQRT2F);
                    }
                    __half2 hh = __floats2half2_rn(v0, v1);
                    tileo[(warpM * 64 + gx) * 68 + warpN * (NF * 4) + nf * 4 + t] =
                        *reinterpret_cast<uint32_t*>(&hh);
                }
            }
        __syncthreads();
        uint32_t* D = (uint32_t*)outp + ((size_t)n * 4096 + rowBase * 64) * 128 + (coBase >> 1);
#pragma unroll 4
        for (int i = tid; i < TH * 64 * (COW / 2); i += 256) {
            int p = i / (COW / 2), j = i % (COW / 2);
            D[(size_t)p * 128 + j] = tileo[p * 68 + j];
        }
        return;
    }

    // ---- fp32 NCHW epilogue: bias + leaky*sqrt2 [+ inline bilinear skip add, /sqrt2] ----
    const int gy = rowBase + warpM;
    int ha = 0, hb = 0; float fha = 0.f, fhb = 0.f;
    if (FUSE) up_taps(gy, 63, ha, hb, fha, fhb);

#pragma unroll
    for (int nf = 0; nf < NF; nf++) {
#pragma unroll
        for (int q = 0; q < 2; q++) {
            const int co = coBase + warpN * (NF * 8) + nf * 8 + t * 2 + q;
            const float bv = ACT ? __ldg(&bias[co]) : 0.f;
            const float* S = FUSE ? (skip64 + ((size_t)n * 128 + co) * 4096) : nullptr;
#pragma unroll
            for (int mf = 0; mf < 4; mf++) {
                const int cb = mf * 16 + g;
#pragma unroll
                for (int h = 0; h < 2; h++) {
                    const int gx = colBase + cb + h * 8;
                    float v = acc[mf][nf][h * 2 + q] + bv;
                    if (ACT) v *= (v >= 0.f) ? SQRT2F : (0.2f * SQRT2F);
                    size_t oidx = (((size_t)n * COUT + co) * W + gy) * W + gx;
                    if (FUSE) {
                        int wa, wb; float fwa, fwb;
                        up_taps(gx, 63, wa, wb, fwa, fwb);
                        float sk = fha * (fwa * S[ha * 64 + wa] + fwb * S[ha * 64 + wb]) +
                                   fhb * (fwa * S[hb * 64 + wa] + fwb * S[hb * 64 + wb]);
                        v = (v + sk) * INV_SQRT2F;
                    }
                    outp[oidx] = v;
                }
            }
        }
    }
}

// ---------------- launch ----------------
extern "C" void kernel_launch(void* const* d_in, const int* in_sizes, int n_in,
                              void* d_out, int out_size)
{
    const float* x   = (const float*)d_in[0];
    const float* w1  = (const float*)d_in[1];
    const float* b1  = (const float*)d_in[2];
    const float* w2  = (const float*)d_in[3];
    const float* b2  = (const float*)d_in[4];
    const float* wsk = (const float*)d_in[5];
    float* out = (float*)d_out;

    void *p0, *p1, *p2, *p3, *p4, *p5, *p6;
    cudaGetSymbolAddress(&p0, g_xh);
    cudaGetSymbolAddress(&p1, g_t1h);
    cudaGetSymbolAddress(&p2, g_uph);
    cudaGetSymbolAddress(&p3, g_skip);
    cudaGetSymbolAddress(&p4, g_w1L);
    cudaGetSymbolAddress(&p5, g_w2L);
    cudaGetSymbolAddress(&p6, g_wskL);
    __half*   xh   = (__half*)p0;
    __half*   t1h  = (__half*)p1;
    __half*   uph  = (__half*)p2;
    float*    skip = (float*)p3;
    uint32_t* w1L  = (uint32_t*)p4;
    uint32_t* w2L  = (uint32_t*)p5;
    uint32_t* wskL = (uint32_t*)p6;

    auto kconv1 = conv_lds<4, 64, 3, 256, 8, true, false, true>;
    auto kconv2 = conv_lds<4, 128, 3, 128, 8, true, true, false>;
    auto kskip  = conv_lds<4, 64, 1, 128, 4, false, false, false>;

    constexpr int SM_CV = 3 * (9 * 128 * 12 + 6 * 66 * 12) * 4;  // 222912
    constexpr int SM_SK = 3 * (1 * 64 * 12 + 4 * 64 * 12) * 4;   // 46080
    cudaFuncSetAttribute(kconv1, cudaFuncAttributeMaxDynamicSharedMemorySize, SM_CV);
    cudaFuncSetAttribute(kconv2, cudaFuncAttributeMaxDynamicSharedMemorySize, SM_CV);
    cudaFuncSetAttribute(kskip,  cudaFuncAttributeMaxDynamicSharedMemorySize, SM_SK);

    // prep
    pack_x_nhwc<<<dim3(128, 8, 8), dim3(32, 8)>>>(x, xh);
    wL_prep<<<1152, 256>>>(w1, w1L, 9, 1.0f / 48.0f, 128, 2 * 16 * 9 * 128 * 8);
    wL_prep<<<576, 256>>>(w2, w2L, 9, 1.0f / 48.0f, 128, 1 * 16 * 9 * 128 * 8);
    wL_prep<<<64, 256>>>(wsk, wskL, 1, 1.0f / 16.0f, 64, 2 * 16 * 1 * 64 * 8);

    // skip 1x1 at 64^2 (upsample commuted; applied inline in conv2 epilogue)
    kskip<<<dim3(16, 2, 8), 256, SM_SK>>>(xh, wskL, nullptr, nullptr, skip);

    // conv1 + FusedLeakyReLU at 64^2 -> NHWC f16 directly
    kconv1<<<dim3(16, 2, 8), 256, SM_CV>>>(xh, w1L, b1, nullptr, (float*)t1h);

    // bilinear 2x upsample, pure f16 NHWC -> f16 NHWC
    upsample_h16<<<65536, 256>>>((const uint32_t*)t1h, (uint32_t*)uph);

    // conv2 + FusedLeakyReLU at 128^2, fused bilinear-skip add + /sqrt(2)
    kconv2<<<dim3(64, 1, 8), 256, SM_CV>>>(uph, w2L, b2, skip, out);
}

// round 16
// speedup vs baseline: 1.0968x; 1.0968x over previous
#include <cuda_runtime.h>
#include <cuda_fp16.h>
#include <cstdint>

#define SQRT2F 1.41421356237309515f
#define INV_SQRT2F 0.70710678118654752f

// ---------------- scratch ----------------
__device__ __align__(16) __half   g_xh  [8ull * 4096 * 256];     // x NHWC f16
__device__ __align__(16) __half   g_t1h [8ull * 4096 * 256];     // conv1 out NHWC f16
__device__ __align__(16) __half   g_uph [8ull * 16384 * 256];    // upsampled NHWC f16
__device__ __align__(16) __half   g_skip[8ull * 128 * 64 * 64];  // skip 64^2 f16 NCHW
__device__ __align__(16) uint32_t g_w1L [4ull * 16 * 9 * 768];   // padded smem-image weights
__device__ __align__(16) uint32_t g_w2L [2ull * 16 * 9 * 768];
__device__ __align__(16) uint32_t g_wskL[2ull * 16 * 1 * 768];

// ---------------- helpers ----------------
__device__ __forceinline__ uint32_t smem_u32(const void* p)
{ return (uint32_t)__cvta_generic_to_shared(p); }

__device__ __forceinline__ void mma_f16(float* c, const uint32_t* a, const uint32_t* b)
{
    asm volatile(
        "mma.sync.aligned.m16n8k16.row.col.f32.f16.f16.f32 "
        "{%0,%1,%2,%3}, {%4,%5,%6,%7}, {%8,%9}, {%0,%1,%2,%3};"
        : "+f"(c[0]), "+f"(c[1]), "+f"(c[2]), "+f"(c[3])
        : "r"(a[0]), "r"(a[1]), "r"(a[2]), "r"(a[3]), "r"(b[0]), "r"(b[1]));
}

__device__ __forceinline__ void ldsm4(uint32_t* r, uint32_t addr)
{
    asm volatile("ldmatrix.sync.aligned.m8n8.x4.shared.b16 {%0,%1,%2,%3}, [%4];"
                 : "=r"(r[0]), "=r"(r[1]), "=r"(r[2]), "=r"(r[3]) : "r"(addr));
}

__device__ __forceinline__ void cp16(void* d, const void* s)
{ asm volatile("cp.async.cg.shared.global [%0], [%1], 16;" :: "r"(smem_u32(d)), "l"(s)); }
__device__ __forceinline__ void cp16z(void* d, const void* s, bool ok)
{ int sz = ok ? 16 : 0;
  asm volatile("cp.async.cg.shared.global [%0], [%1], 16, %2;" :: "r"(smem_u32(d)), "l"(s), "r"(sz)); }
__device__ __forceinline__ void cpc() { asm volatile("cp.async.commit_group;"); }
template <int N> __device__ __forceinline__ void cpw()
{ asm volatile("cp.async.wait_group %0;" :: "n"(N)); }

__device__ __forceinline__ void up_taps(int o, int lim, int& a, int& b, float& fa, float& fb)
{
    int i = o >> 1;
    if (o & 1) { a = i; b = (i + 1 < lim) ? i + 1 : lim; fa = 0.75f; fb = 0.25f; }
    else       { a = (i - 1 > 0) ? i - 1 : 0; b = i;     fa = 0.25f; fb = 0.75f; }
}

// ---------------- prep: x NCHW fp32 -> NHWC f16 ----------------
__global__ void pack_x_nhwc(const float* __restrict__ src, __half* __restrict__ dst)
{
    __shared__ float tile[32][33];
    int n = blockIdx.z, c0 = blockIdx.y * 32, p0 = blockIdx.x * 32;
    int tx = threadIdx.x, ty = threadIdx.y;
    const float* S = src + (size_t)n * 256 * 4096;
    __half* D = dst + (size_t)n * 4096 * 256;
#pragma unroll
    for (int i = 0; i < 32; i += 8) tile[ty + i][tx] = S[(size_t)(c0 + ty + i) * 4096 + p0 + tx];
    __syncthreads();
#pragma unroll
    for (int i = 0; i < 32; i += 8)
        D[(size_t)(p0 + ty + i) * 256 + c0 + tx] = __float2half(tile[tx][ty + i]);
}

// ---------------- prep: weights -> padded co-major smem image ----------------
__global__ void wL_prep(const float* __restrict__ w, uint32_t* __restrict__ dst,
                        int ks2, float scale, int total)
{
    int idx = blockIdx.x * 256 + threadIdx.x;
    if (idx >= total) return;
    int j  = idx & 7;
    int t1 = idx >> 3;
    int co = t1 & 63;
    int t2 = t1 >> 6;
    int tap   = t2 % ks2;
    int t3    = t2 / ks2;
    int chunk = t3 & 15;
    int coblk = t3 >> 4;
    int cog = coblk * 64 + co;
    int ci  = chunk * 16 + 2 * j;
    float lo = w[((size_t)cog * 256 + ci) * ks2 + tap] * scale;
    float hi = w[((size_t)cog * 256 + ci + 1) * ks2 + tap] * scale;
    __half2 h = __floats2half2_rn(lo, hi);
    dst[(size_t)t2 * 768 + co * 12 + j] = *reinterpret_cast<uint32_t*>(&h);
}

// ---------------- upsample: NHWC f16 64^2 -> NHWC f16 128^2 ----------------
__global__ void upsample_h16(const uint32_t* __restrict__ src, uint32_t* __restrict__ dst)
{
    int idx = blockIdx.x * 256 + threadIdx.x;   // 16777216 exact
    int n = idx >> 21, rem = idx & 2097151;
    int px = rem >> 7, j = rem & 127;
    int oh = px >> 7, ow = px & 127;
    int ha, hb, wa, wb; float fha, fhb, fwa, fwb;
    up_taps(oh, 63, ha, hb, fha, fhb);
    up_taps(ow, 63, wa, wb, fwa, fwb);
    const uint32_t* S = src + (size_t)n * 4096 * 128;
    float2 aa = __half22float2(*(const __half2*)&S[(ha * 64 + wa) * 128 + j]);
    float2 ab = __half22float2(*(const __half2*)&S[(ha * 64 + wb) * 128 + j]);
    float2 ba = __half22float2(*(const __half2*)&S[(hb * 64 + wa) * 128 + j]);
    float2 bb = __half22float2(*(const __half2*)&S[(hb * 64 + wb) * 128 + j]);
    float v0 = fha * (fwa * aa.x + fwb * ab.x) + fhb * (fwa * ba.x + fwb * bb.x);
    float v1 = fha * (fwa * aa.y + fwb * ab.y) + fhb * (fwa * ba.y + fwb * bb.y);
    __half2 h = __floats2half2_rn(v0, v1);
    dst[idx] = *reinterpret_cast<uint32_t*>(&h);
}

// ---------------- f16 implicit-GEMM conv: ldmatrix + mma.sync, cp.async pipeline ----
// Block: 256 thr (8 warps). Tile: (TH rows x 64 cols) px x 64 co. 2 CTAs/SM.
// OUT16: NHWC f16 out via smem transpose. OUTH: NCHW f16 out (skip kernel).
template <int TH, int W, int KS, int COUT, bool ACT, bool FUSE, bool OUT16, bool OUTH>
__global__ __launch_bounds__(256, 2)
void conv_lds(const __half* __restrict__ xin, const uint32_t* __restrict__ wL,
              const float* __restrict__ bias, const __half* __restrict__ skip64,
              float* __restrict__ outp)
{
    constexpr int KS2   = KS * KS;
    constexpr int PAD   = (KS == 3) ? 1 : 0;
    constexpr int XR    = TH + KS - 1;
    constexpr int CW    = 64 + 2 * PAD;
    constexpr int WSTG  = KS2 * 768;          // u32
    constexpr int XSTG  = XR * CW * 12;       // u32
    constexpr int STAGE = WSTG + XSTG;
    constexpr int NCH   = 16;

    extern __shared__ uint32_t smemu[];

    const int tid = threadIdx.x, lane = tid & 31, warp = tid >> 5;
    const int warpM = warp & 3, warpN = warp >> 2;
    const int n = blockIdx.z, coBase = blockIdx.y * 64;
    constexpr int tilesX = W / 64;
    const int colBase = (blockIdx.x % tilesX) * 64;
    const int rowBase = (blockIdx.x / tilesX) * TH;

    const __half* xN = xin + (size_t)n * W * W * 256;

    const int aLane = ((lane & 7) + ((lane >> 3) & 1) * 8) * 12 + (lane >> 4) * 4;
    const int bLane = ((lane & 7) + (lane >> 4) * 8) * 12 + ((lane >> 3) & 1) * 4;

    auto stage = [&](int ch) {
        uint32_t* base = smemu + (ch & 1) * STAGE;
        uint32_t* Wsb = base;
        uint32_t* Xsb = base + WSTG;
        const uint32_t* ws = wL + ((size_t)(blockIdx.y * 16 + ch) * KS2) * 768;
#pragma unroll
        for (int i = tid; i < KS2 * 128; i += 256) {
            int c16 = i & 1, co = (i >> 1) & 63, tap = i >> 7;
            int off = tap * 768 + co * 12 + c16 * 4;
            cp16(Wsb + off, ws + off);
        }
        const int ciB = ch * 16;
#pragma unroll
        for (int i = tid; i < XR * CW * 2; i += 256) {
            int p = i >> 1, g8 = i & 1;
            int hr = p / CW, hc = p - hr * CW;
            int gy = rowBase + hr - PAD, gx = colBase + hc - PAD;
            bool ok = ((unsigned)gy < (unsigned)W) && ((unsigned)gx < (unsigned)W);
            const __half* s = ok ? xN + ((size_t)gy * W + gx) * 256 + ciB + g8 * 8 : xN;
            cp16z(Xsb + p * 12 + g8 * 4, s, ok);
        }
    };

    float acc[4][4][4];
#pragma unroll
    for (int i = 0; i < 4; i++)
#pragma unroll
        for (int j = 0; j < 4; j++)
#pragma unroll
            for (int k = 0; k < 4; k++) acc[i][j][k] = 0.f;

    stage(0); cpc();
    stage(1); cpc();

    for (int c = 0; c < NCH; c++) {
        if (c + 1 < NCH) cpw<1>(); else cpw<0>();
        __syncthreads();

        uint32_t* base = smemu + (c & 1) * STAGE;
        const uint32_t wB0 = smem_u32(base) + bLane * 4;
        const uint32_t xB0 = smem_u32(base + WSTG) + aLane * 4;

#pragma unroll
        for (int ky = 0; ky < KS; ky++)
#pragma unroll
            for (int kx = 0; kx < KS; kx++) {
                const int tap = ky * KS + kx;
                const int rowOff = ((warpM + ky) * CW + kx) * 48;
                uint32_t a[4][4], bf[4][2];
#pragma unroll
                for (int mf = 0; mf < 4; mf++)
                    ldsm4(a[mf], xB0 + rowOff + mf * 768);
#pragma unroll
                for (int np = 0; np < 2; np++) {
                    uint32_t r[4];
                    ldsm4(r, wB0 + tap * 3072 + (warpN * 32 + np * 16) * 48);
                    bf[np * 2][0] = r[0]; bf[np * 2][1] = r[1];
                    bf[np * 2 + 1][0] = r[2]; bf[np * 2 + 1][1] = r[3];
                }
#pragma unroll
                for (int mf = 0; mf < 4; mf++)
#pragma unroll
                    for (int nf = 0; nf < 4; nf++)
                        mma_f16(acc[mf][nf], a[mf], bf[nf]);
            }
        __syncthreads();

        if (c + 2 < NCH) { stage(c + 2); cpc(); }
    }

    const int g = lane >> 2, t = lane & 3;

    if (OUT16) {
        // NHWC f16 out via smem transpose (stride 36 u32/px -> banks 4g+t, conflict-free)
        uint32_t* tileo = smemu;
        float bv0[4], bv1[4];
#pragma unroll
        for (int nf = 0; nf < 4; nf++) {
            int co = coBase + warpN * 32 + nf * 8 + t * 2;
            bv0[nf] = ACT ? __ldg(&bias[co]) : 0.f;
            bv1[nf] = ACT ? __ldg(&bias[co + 1]) : 0.f;
        }
#pragma unroll
        for (int mf = 0; mf < 4; mf++)
#pragma unroll
            for (int h = 0; h < 2; h++) {
                const int gx = mf * 16 + g + h * 8;
#pragma unroll
                for (int nf = 0; nf < 4; nf++) {
                    float v0 = acc[mf][nf][h * 2 + 0] + bv0[nf];
                    float v1 = acc[mf][nf][h * 2 + 1] + bv1[nf];
                    if (ACT) {
                        v0 *= (v0 >= 0.f) ? SQRT2F : (0.2f * SQRT2F);
                        v1 *= (v1 >= 0.f) ? SQRT2F : (0.2f * SQRT2F);
                    }
                    __half2 hh = __floats2half2_rn(v0, v1);
                    tileo[(warpM * 64 + gx) * 36 + warpN * 16 + nf * 4 + t] =
                        *reinterpret_cast<uint32_t*>(&hh);
                }
            }
        __syncthreads();
        uint32_t* D = (uint32_t*)outp + ((size_t)n * 4096 + rowBase * 64) * 128 + (coBase >> 1);
#pragma unroll 4
        for (int i = tid; i < TH * 64 * 32; i += 256) {
            int p = i >> 5, j = i & 31;
            D[(size_t)p * 128 + j] = tileo[p * 36 + j];
        }
        return;
    }

    // ---- NCHW epilogue: bias + leaky*sqrt2 [+ inline bilinear f16-skip add, /sqrt2] ----
    const int gy = rowBase + warpM;
    int ha = 0, hb = 0; float fha = 0.f, fhb = 0.f;
    if (FUSE) up_taps(gy, 63, ha, hb, fha, fhb);

#pragma unroll
    for (int nf = 0; nf < 4; nf++) {
#pragma unroll
        for (int q = 0; q < 2; q++) {
            const int co = coBase + warpN * 32 + nf * 8 + t * 2 + q;
            const float bv = ACT ? __ldg(&bias[co]) : 0.f;
            const __half* S = FUSE ? (skip64 + ((size_t)n * 128 + co) * 4096) : nullptr;
#pragma unroll
            for (int mf = 0; mf < 4; mf++) {
                const int cb = mf * 16 + g;
#pragma unroll
                for (int h = 0; h < 2; h++) {
                    const int gx = colBase + cb + h * 8;
                    float v = acc[mf][nf][h * 2 + q] + bv;
                    if (ACT) v *= (v >= 0.f) ? SQRT2F : (0.2f * SQRT2F);
                    size_t oidx = (((size_t)n * COUT + co) * W + gy) * W + gx;
                    if (FUSE) {
                        int wa, wb; float fwa, fwb;
                        up_taps(gx, 63, wa, wb, fwa, fwb);
                        float sk = fha * (fwa * __half2float(S[ha * 64 + wa]) +
                                          fwb * __half2float(S[ha * 64 + wb])) +
                                   fhb * (fwa * __half2float(S[hb * 64 + wa]) +
                                          fwb * __half2float(S[hb * 64 + wb]));
                        v = (v + sk) * INV_SQRT2F;
                    }
                    if (OUTH) ((__half*)outp)[oidx] = __float2half(v);
                    else      outp[oidx] = v;
                }
            }
        }
    }
}

// ---------------- launch ----------------
extern "C" void kernel_launch(void* const* d_in, const int* in_sizes, int n_in,
                              void* d_out, int out_size)
{
    const float* x   = (const float*)d_in[0];
    const float* w1  = (const float*)d_in[1];
    const float* b1  = (const float*)d_in[2];
    const float* w2  = (const float*)d_in[3];
    const float* b2  = (const float*)d_in[4];
    const float* wsk = (const float*)d_in[5];
    float* out = (float*)d_out;

    void *p0, *p1, *p2, *p3, *p4, *p5, *p6;
    cudaGetSymbolAddress(&p0, g_xh);
    cudaGetSymbolAddress(&p1, g_t1h);
    cudaGetSymbolAddress(&p2, g_uph);
    cudaGetSymbolAddress(&p3, g_skip);
    cudaGetSymbolAddress(&p4, g_w1L);
    cudaGetSymbolAddress(&p5, g_w2L);
    cudaGetSymbolAddress(&p6, g_wskL);
    __half*   xh   = (__half*)p0;
    __half*   t1h  = (__half*)p1;
    __half*   uph  = (__half*)p2;
    __half*   skip = (__half*)p3;
    uint32_t* w1L  = (uint32_t*)p4;
    uint32_t* w2L  = (uint32_t*)p5;
    uint32_t* wskL = (uint32_t*)p6;

    auto kconv1 = conv_lds<4, 64, 3, 256, true, false, true, false>;
    auto kconv2 = conv_lds<4, 128, 3, 128, true, true, false, false>;
    auto kskip  = conv_lds<4, 64, 1, 128, false, false, false, true>;

    constexpr int SM_CV = 2 * (9 * 768 + 6 * 66 * 12) * 4;   // 93312
    constexpr int SM_SK = 2 * (1 * 768 + 4 * 64 * 12) * 4;   // 30720
    cudaFuncSetAttribute(kconv1, cudaFuncAttributeMaxDynamicSharedMemorySize, SM_CV);
    cudaFuncSetAttribute(kconv2, cudaFuncAttributeMaxDynamicSharedMemorySize, SM_CV);
    cudaFuncSetAttribute(kskip,  cudaFuncAttributeMaxDynamicSharedMemorySize, SM_SK);

    // prep
    pack_x_nhwc<<<dim3(128, 8, 8), dim3(32, 8)>>>(x, xh);
    wL_prep<<<1152, 256>>>(w1, w1L, 9, 1.0f / 48.0f, 4 * 16 * 9 * 64 * 8);
    wL_prep<<<576, 256>>>(w2, w2L, 9, 1.0f / 48.0f, 2 * 16 * 9 * 64 * 8);
    wL_prep<<<64, 256>>>(wsk, wskL, 1, 1.0f / 16.0f, 2 * 16 * 1 * 64 * 8);

    // skip 1x1 at 64^2 -> f16 NCHW (upsample commuted; applied inline in conv2 epilogue)
    kskip<<<dim3(16, 2, 8), 256, SM_SK>>>(xh, wskL, nullptr, nullptr, (float*)skip);

    // conv1 + FusedLeakyReLU at 64^2 -> NHWC f16 directly
    kconv1<<<dim3(16, 4, 8), 256, SM_CV>>>(xh, w1L, b1, nullptr, (float*)t1h);

    // bilinear 2x upsample, pure f16 NHWC -> f16 NHWC
    upsample_h16<<<65536, 256>>>((const uint32_t*)t1h, (uint32_t*)uph);

    // conv2 + FusedLeakyReLU at 128^2, fused f16 bilinear-skip add + /sqrt(2)
    kconv2<<<dim3(64, 2, 8), 256, SM_CV>>>(uph, w2L, b2, skip, out);
}

// round 17
// speedup vs baseline: 1.1692x; 1.0660x over previous
#include <cuda_runtime.h>
#include <cuda_fp16.h>
#include <cstdint>

#define SQRT2F 1.41421356237309515f
#define INV_SQRT2F 0.70710678118654752f

// ---------------- scratch ----------------
__device__ __align__(16) __half   g_xh  [8ull * 4096 * 256];     // x NHWC f16
__device__ __align__(16) __half   g_t1h [8ull * 4096 * 256];     // conv1 out NHWC f16
__device__ __align__(16) __half   g_uph [8ull * 16384 * 256];    // upsampled NHWC f16
__device__ __align__(16) __half   g_skip[8ull * 128 * 64 * 64];  // skip 64^2 f16 NCHW
__device__ __align__(16) uint32_t g_w1L [4ull * 16 * 9 * 768];   // padded smem-image weights
__device__ __align__(16) uint32_t g_w2L [2ull * 16 * 9 * 768];
__device__ __align__(16) uint32_t g_wskL[2ull * 16 * 1 * 768];

// ---------------- helpers ----------------
__device__ __forceinline__ uint32_t smem_u32(const void* p)
{ return (uint32_t)__cvta_generic_to_shared(p); }

__device__ __forceinline__ void mma_f16(float* c, const uint32_t* a, const uint32_t* b)
{
    asm volatile(
        "mma.sync.aligned.m16n8k16.row.col.f32.f16.f16.f32 "
        "{%0,%1,%2,%3}, {%4,%5,%6,%7}, {%8,%9}, {%0,%1,%2,%3};"
        : "+f"(c[0]), "+f"(c[1]), "+f"(c[2]), "+f"(c[3])
        : "r"(a[0]), "r"(a[1]), "r"(a[2]), "r"(a[3]), "r"(b[0]), "r"(b[1]));
}

__device__ __forceinline__ void ldsm4(uint32_t* r, uint32_t addr)
{
    asm volatile("ldmatrix.sync.aligned.m8n8.x4.shared.b16 {%0,%1,%2,%3}, [%4];"
                 : "=r"(r[0]), "=r"(r[1]), "=r"(r[2]), "=r"(r[3]) : "r"(addr));
}

__device__ __forceinline__ void cp16(void* d, const void* s)
{ asm volatile("cp.async.cg.shared.global [%0], [%1], 16;" :: "r"(smem_u32(d)), "l"(s)); }
__device__ __forceinline__ void cp16z(void* d, const void* s, bool ok)
{ int sz = ok ? 16 : 0;
  asm volatile("cp.async.cg.shared.global [%0], [%1], 16, %2;" :: "r"(smem_u32(d)), "l"(s), "r"(sz)); }
__device__ __forceinline__ void cpc() { asm volatile("cp.async.commit_group;"); }
template <int N> __device__ __forceinline__ void cpw()
{ asm volatile("cp.async.wait_group %0;" :: "n"(N)); }

__device__ __forceinline__ void up_taps(int o, int lim, int& a, int& b, float& fa, float& fb)
{
    int i = o >> 1;
    if (o & 1) { a = i; b = (i + 1 < lim) ? i + 1 : lim; fa = 0.75f; fb = 0.25f; }
    else       { a = (i - 1 > 0) ? i - 1 : 0; b = i;     fa = 0.25f; fb = 0.75f; }
}

// ---------------- prep: x NCHW fp32 -> NHWC f16 ----------------
__global__ void pack_x_nhwc(const float* __restrict__ src, __half* __restrict__ dst)
{
    __shared__ float tile[32][33];
    int n = blockIdx.z, c0 = blockIdx.y * 32, p0 = blockIdx.x * 32;
    int tx = threadIdx.x, ty = threadIdx.y;
    const float* S = src + (size_t)n * 256 * 4096;
    __half* D = dst + (size_t)n * 4096 * 256;
#pragma unroll
    for (int i = 0; i < 32; i += 8) tile[ty + i][tx] = S[(size_t)(c0 + ty + i) * 4096 + p0 + tx];
    __syncthreads();
#pragma unroll
    for (int i = 0; i < 32; i += 8)
        D[(size_t)(p0 + ty + i) * 256 + c0 + tx] = __float2half(tile[tx][ty + i]);
}

// ---------------- prep: all weights -> padded co-major smem images (one launch) ----------
__device__ __forceinline__ void w_prep_one(const float* __restrict__ w,
                                           uint32_t* __restrict__ dst,
                                           int ks2, float scale, int idx)
{
    int j  = idx & 7;
    int t1 = idx >> 3;
    int co = t1 & 63;
    int t2 = t1 >> 6;
    int tap   = t2 % ks2;
    int t3    = t2 / ks2;
    int chunk = t3 & 15;
    int coblk = t3 >> 4;
    int cog = coblk * 64 + co;
    int ci  = chunk * 16 + 2 * j;
    float lo = w[((size_t)cog * 256 + ci) * ks2 + tap] * scale;
    float hi = w[((size_t)cog * 256 + ci + 1) * ks2 + tap] * scale;
    __half2 h = __floats2half2_rn(lo, hi);
    dst[(size_t)t2 * 768 + co * 12 + j] = *reinterpret_cast<uint32_t*>(&h);
}

#define W1_TOT (4 * 16 * 9 * 64 * 8)
#define W2_TOT (2 * 16 * 9 * 64 * 8)
#define WSK_TOT (2 * 16 * 1 * 64 * 8)

__global__ void wL_prep_all(const float* __restrict__ w1, const float* __restrict__ w2,
                            const float* __restrict__ wsk,
                            uint32_t* __restrict__ d1, uint32_t* __restrict__ d2,
                            uint32_t* __restrict__ dsk)
{
    int idx = blockIdx.x * 256 + threadIdx.x;
    if (idx < W1_TOT)                       w_prep_one(w1, d1, 9, 1.0f / 48.0f, idx);
    else if (idx < W1_TOT + W2_TOT)         w_prep_one(w2, d2, 9, 1.0f / 48.0f, idx - W1_TOT);
    else if (idx < W1_TOT + W2_TOT + WSK_TOT)
        w_prep_one(wsk, dsk, 1, 1.0f / 16.0f, idx - W1_TOT - W2_TOT);
}

// ---------------- upsample: NHWC f16 64^2 -> NHWC f16 128^2 ----------------
__global__ void upsample_h16(const uint32_t* __restrict__ src, uint32_t* __restrict__ dst)
{
    int idx = blockIdx.x * 256 + threadIdx.x;   // 16777216 exact
    int n = idx >> 21, rem = idx & 2097151;
    int px = rem >> 7, j = rem & 127;
    int oh = px >> 7, ow = px & 127;
    int ha, hb, wa, wb; float fha, fhb, fwa, fwb;
    up_taps(oh, 63, ha, hb, fha, fhb);
    up_taps(ow, 63, wa, wb, fwa, fwb);
    const uint32_t* S = src + (size_t)n * 4096 * 128;
    float2 aa = __half22float2(*(const __half2*)&S[(ha * 64 + wa) * 128 + j]);
    float2 ab = __half22float2(*(const __half2*)&S[(ha * 64 + wb) * 128 + j]);
    float2 ba = __half22float2(*(const __half2*)&S[(hb * 64 + wa) * 128 + j]);
    float2 bb = __half22float2(*(const __half2*)&S[(hb * 64 + wb) * 128 + j]);
    float v0 = fha * (fwa * aa.x + fwb * ab.x) + fhb * (fwa * ba.x + fwb * bb.x);
    float v1 = fha * (fwa * aa.y + fwb * ab.y) + fhb * (fwa * ba.y + fwb * bb.y);
    __half2 h = __floats2half2_rn(v0, v1);
    dst[idx] = *reinterpret_cast<uint32_t*>(&h);
}

// ---------------- f16 implicit-GEMM conv body (device fn, proven R12 config) ----------
// Block: 256 thr (8 warps). Tile: (TH rows x 64 cols) px x 64 co. 2 CTAs/SM.
template <int TH, int W, int KS, int COUT, bool ACT, bool FUSE, bool OUT16, bool OUTH>
__device__ __forceinline__
void conv_impl(const __half* __restrict__ xin, const uint32_t* __restrict__ wL,
               const float* __restrict__ bias, const __half* __restrict__ skip64,
               float* __restrict__ outp, int coY)
{
    constexpr int KS2   = KS * KS;
    constexpr int PAD   = (KS == 3) ? 1 : 0;
    constexpr int XR    = TH + KS - 1;
    constexpr int CW    = 64 + 2 * PAD;
    constexpr int WSTG  = KS2 * 768;          // u32
    constexpr int XSTG  = XR * CW * 12;       // u32
    constexpr int STAGE = WSTG + XSTG;
    constexpr int NCH   = 16;

    extern __shared__ uint32_t smemu[];

    const int tid = threadIdx.x, lane = tid & 31, warp = tid >> 5;
    const int warpM = warp & 3, warpN = warp >> 2;
    const int n = blockIdx.z, coBase = coY * 64;
    constexpr int tilesX = W / 64;
    const int colBase = (blockIdx.x % tilesX) * 64;
    const int rowBase = (blockIdx.x / tilesX) * TH;

    const __half* xN = xin + (size_t)n * W * W * 256;

    const int aLane = ((lane & 7) + ((lane >> 3) & 1) * 8) * 12 + (lane >> 4) * 4;
    const int bLane = ((lane & 7) + (lane >> 4) * 8) * 12 + ((lane >> 3) & 1) * 4;

    auto stage = [&](int ch) {
        uint32_t* base = smemu + (ch & 1) * STAGE;
        uint32_t* Wsb = base;
        uint32_t* Xsb = base + WSTG;
        const uint32_t* ws = wL + ((size_t)(coY * 16 + ch) * KS2) * 768;
#pragma unroll
        for (int i = tid; i < KS2 * 128; i += 256) {
            int c16 = i & 1, co = (i >> 1) & 63, tap = i >> 7;
            int off = tap * 768 + co * 12 + c16 * 4;
            cp16(Wsb + off, ws + off);
        }
        const int ciB = ch * 16;
#pragma unroll
        for (int i = tid; i < XR * CW * 2; i += 256) {
            int p = i >> 1, g8 = i & 1;
            int hr = p / CW, hc = p - hr * CW;
            int gy = rowBase + hr - PAD, gx = colBase + hc - PAD;
            bool ok = ((unsigned)gy < (unsigned)W) && ((unsigned)gx < (unsigned)W);
            const __half* s = ok ? xN + ((size_t)gy * W + gx) * 256 + ciB + g8 * 8 : xN;
            cp16z(Xsb + p * 12 + g8 * 4, s, ok);
        }
    };

    float acc[4][4][4];
#pragma unroll
    for (int i = 0; i < 4; i++)
#pragma unroll
        for (int j = 0; j < 4; j++)
#pragma unroll
            for (int k = 0; k < 4; k++) acc[i][j][k] = 0.f;

    stage(0); cpc();
    stage(1); cpc();

    for (int c = 0; c < NCH; c++) {
        if (c + 1 < NCH) cpw<1>(); else cpw<0>();
        __syncthreads();

        uint32_t* base = smemu + (c & 1) * STAGE;
        const uint32_t wB0 = smem_u32(base) + bLane * 4;
        const uint32_t xB0 = smem_u32(base + WSTG) + aLane * 4;

#pragma unroll
        for (int ky = 0; ky < KS; ky++)
#pragma unroll
            for (int kx = 0; kx < KS; kx++) {
                const int tap = ky * KS + kx;
                const int rowOff = ((warpM + ky) * CW + kx) * 48;
                uint32_t a[4][4], bf[4][2];
#pragma unroll
                for (int mf = 0; mf < 4; mf++)
                    ldsm4(a[mf], xB0 + rowOff + mf * 768);
#pragma unroll
                for (int np = 0; np < 2; np++) {
                    uint32_t r[4];
                    ldsm4(r, wB0 + tap * 3072 + (warpN * 32 + np * 16) * 48);
                    bf[np * 2][0] = r[0]; bf[np * 2][1] = r[1];
                    bf[np * 2 + 1][0] = r[2]; bf[np * 2 + 1][1] = r[3];
                }
#pragma unroll
                for (int mf = 0; mf < 4; mf++)
#pragma unroll
                    for (int nf = 0; nf < 4; nf++)
                        mma_f16(acc[mf][nf], a[mf], bf[nf]);
            }
        __syncthreads();

        if (c + 2 < NCH) { stage(c + 2); cpc(); }
    }

    const int g = lane >> 2, t = lane & 3;

    if (OUT16) {
        // NHWC f16 out via smem transpose (stride 36 u32/px -> banks 4g+t, conflict-free)
        uint32_t* tileo = smemu;
        float bv0[4], bv1[4];
#pragma unroll
        for (int nf = 0; nf < 4; nf++) {
            int co = coBase + warpN * 32 + nf * 8 + t * 2;
            bv0[nf] = ACT ? __ldg(&bias[co]) : 0.f;
            bv1[nf] = ACT ? __ldg(&bias[co + 1]) : 0.f;
        }
#pragma unroll
        for (int mf = 0; mf < 4; mf++)
#pragma unroll
            for (int h = 0; h < 2; h++) {
                const int gx = mf * 16 + g + h * 8;
#pragma unroll
                for (int nf = 0; nf < 4; nf++) {
                    float v0 = acc[mf][nf][h * 2 + 0] + bv0[nf];
                    float v1 = acc[mf][nf][h * 2 + 1] + bv1[nf];
                    if (ACT) {
                        v0 *= (v0 >= 0.f) ? SQRT2F : (0.2f * SQRT2F);
                        v1 *= (v1 >= 0.f) ? SQRT2F : (0.2f * SQRT2F);
                    }
                    __half2 hh = __floats2half2_rn(v0, v1);
                    tileo[(warpM * 64 + gx) * 36 + warpN * 16 + nf * 4 + t] =
                        *reinterpret_cast<uint32_t*>(&hh);
                }
            }
        __syncthreads();
        uint32_t* D = (uint32_t*)outp + ((size_t)n * 4096 + rowBase * 64) * 128 + (coBase >> 1);
#pragma unroll 4
        for (int i = tid; i < TH * 64 * 32; i += 256) {
            int p = i >> 5, j = i & 31;
            D[(size_t)p * 128 + j] = tileo[p * 36 + j];
        }
        return;
    }

    // ---- NCHW epilogue: bias + leaky*sqrt2 [+ inline bilinear f16-skip add, /sqrt2] ----
    const int gy = rowBase + warpM;
    int ha = 0, hb = 0; float fha = 0.f, fhb = 0.f;
    if (FUSE) up_taps(gy, 63, ha, hb, fha, fhb);

#pragma unroll
    for (int nf = 0; nf < 4; nf++) {
#pragma unroll
        for (int q = 0; q < 2; q++) {
            const int co = coBase + warpN * 32 + nf * 8 + t * 2 + q;
            const float bv = ACT ? __ldg(&bias[co]) : 0.f;
            const __half* S = FUSE ? (skip64 + ((size_t)n * 128 + co) * 4096) : nullptr;
#pragma unroll
            for (int mf = 0; mf < 4; mf++) {
                const int cb = mf * 16 + g;
#pragma unroll
                for (int h = 0; h < 2; h++) {
                    const int gx = colBase + cb + h * 8;
                    float v = acc[mf][nf][h * 2 + q] + bv;
                    if (ACT) v *= (v >= 0.f) ? SQRT2F : (0.2f * SQRT2F);
                    size_t oidx = (((size_t)n * COUT + co) * W + gy) * W + gx;
                    if (FUSE) {
                        int wa, wb; float fwa, fwb;
                        up_taps(gx, 63, wa, wb, fwa, fwb);
                        float sk = fha * (fwa * __half2float(S[ha * 64 + wa]) +
                                          fwb * __half2float(S[ha * 64 + wb])) +
                                   fhb * (fwa * __half2float(S[hb * 64 + wa]) +
                                          fwb * __half2float(S[hb * 64 + wb]));
                        v = (v + sk) * INV_SQRT2F;
                    }
                    if (OUTH) ((__half*)outp)[oidx] = __float2half(v);
                    else      outp[oidx] = v;
                }
            }
        }
    }
}

// ---- merged conv1 + skip launch: y<4 -> conv1 co-block; y>=4 -> skip co-block ----
__global__ __launch_bounds__(256, 2)
void conv1_skip_kernel(const __half* __restrict__ xh,
                       const uint32_t* __restrict__ w1L, const float* __restrict__ b1,
                       const uint32_t* __restrict__ wskL,
                       float* __restrict__ t1h, float* __restrict__ skp)
{
    if (blockIdx.y < 4)
        conv_impl<4, 64, 3, 256, true, false, true, false>(xh, w1L, b1, nullptr, t1h,
                                                           blockIdx.y);
    else
        conv_impl<4, 64, 1, 128, false, false, false, true>(xh, wskL, nullptr, nullptr, skp,
                                                            blockIdx.y - 4);
}

__global__ __launch_bounds__(256, 2)
void conv2_kernel(const __half* __restrict__ uph, const uint32_t* __restrict__ w2L,
                  const float* __restrict__ b2, const __half* __restrict__ skp,
                  float* __restrict__ out)
{
    conv_impl<4, 128, 3, 128, true, true, false, false>(uph, w2L, b2, skp, out, blockIdx.y);
}

// ---------------- launch ----------------
extern "C" void kernel_launch(void* const* d_in, const int* in_sizes, int n_in,
                              void* d_out, int out_size)
{
    const float* x   = (const float*)d_in[0];
    const float* w1  = (const float*)d_in[1];
    const float* b1  = (const float*)d_in[2];
    const float* w2  = (const float*)d_in[3];
    const float* b2  = (const float*)d_in[4];
    const float* wsk = (const float*)d_in[5];
    float* out = (float*)d_out;

    void *p0, *p1, *p2, *p3, *p4, *p5, *p6;
    cudaGetSymbolAddress(&p0, g_xh);
    cudaGetSymbolAddress(&p1, g_t1h);
    cudaGetSymbolAddress(&p2, g_uph);
    cudaGetSymbolAddress(&p3, g_skip);
    cudaGetSymbolAddress(&p4, g_w1L);
    cudaGetSymbolAddress(&p5, g_w2L);
    cudaGetSymbolAddress(&p6, g_wskL);
    __half*   xh   = (__half*)p0;
    __half*   t1h  = (__half*)p1;
    __half*   uph  = (__half*)p2;
    __half*   skip = (__half*)p3;
    uint32_t* w1L  = (uint32_t*)p4;
    uint32_t* w2L  = (uint32_t*)p5;
    uint32_t* wskL = (uint32_t*)p6;

    constexpr int SM_CV = 2 * (9 * 768 + 6 * 66 * 12) * 4;   // 93312
    cudaFuncSetAttribute(conv1_skip_kernel, cudaFuncAttributeMaxDynamicSharedMemorySize, SM_CV);
    cudaFuncSetAttribute(conv2_kernel,      cudaFuncAttributeMaxDynamicSharedMemorySize, SM_CV);

    // prep (2 launches total)
    pack_x_nhwc<<<dim3(128, 8, 8), dim3(32, 8)>>>(x, xh);
    wL_prep_all<<<(W1_TOT + W2_TOT + WSK_TOT) / 256, 256>>>(w1, w2, wsk, w1L, w2L, wskL);

    // conv1 + FusedLeakyReLU (-> NHWC f16) and skip 1x1 (-> f16 NCHW), one launch
    conv1_skip_kernel<<<dim3(16, 6, 8), 256, SM_CV>>>(xh, w1L, b1, wskL,
                                                      (float*)t1h, (float*)skip);

    // bilinear 2x upsample, pure f16 NHWC -> f16 NHWC
    upsample_h16<<<65536, 256>>>((const uint32_t*)t1h, (uint32_t*)uph);

    // conv2 + FusedLeakyReLU at 128^2, fused f16 bilinear-skip add + /sqrt(2)
    conv2_kernel<<<dim3(64, 2, 8), 256, SM_CV>>>(uph, w2L, b2, skip, out);
}